// round 1
// baseline (speedup 1.0000x reference)
#include <cuda_runtime.h>
#include <cuda_bf16.h>
#include <cstdint>

#define ND 50000
#define ED 800000
#define DD 128

// ---------------- scratch (device globals; no allocation allowed) ----------------
__device__ float g_deg[ND];
__device__ float g_dinv[ND];
__device__ float g_h[ND * DD];     // x @ W
__device__ float g_agg[ND * DD];   // scatter accumulator
__device__ float g_t[ND * DD];     // pre-BN
__device__ float g_y[ND * DD];     // post layer-1 activation
__device__ float g_stats[2 * DD];  // col sums / sumsq
__device__ float g_scale[DD];
__device__ float g_shift[DD];

// ---------------- init: deg=1, stats=0, agg=0 ----------------
__global__ void k_init(int n) {
    int i = blockIdx.x * blockDim.x + threadIdx.x;
    int n4 = n * (DD / 4);
    if (i < n4) reinterpret_cast<float4*>(g_agg)[i] = make_float4(0.f, 0.f, 0.f, 0.f);
    if (i < n) g_deg[i] = 1.0f;
    if (i < 2 * DD) g_stats[i] = 0.0f;
}

__global__ void k_degree(const int* __restrict__ dst, int e) {
    int i = blockIdx.x * blockDim.x + threadIdx.x;
    if (i < e) atomicAdd(&g_deg[dst[i]], 1.0f);
}

__global__ void k_dinv(int n) {
    int i = blockIdx.x * blockDim.x + threadIdx.x;
    if (i < n) g_dinv[i] = rsqrtf(g_deg[i]);
}

// ---------------- GEMM: H[n,128] = X[n,128] @ W[128,128] ----------------
// 256 threads/block, 64 rows/block. W k-tiled in smem (32x128), X tile (64x32).
// Thread (warp w, lane l): rows w*8..w*8+7, cols l*4..l*4+3.
__global__ __launch_bounds__(256) void k_gemm(const float* __restrict__ X,
                                              const float* __restrict__ W,
                                              float* __restrict__ H, int nrows) {
    __shared__ float sW[32 * 128];
    __shared__ float sX[64 * 32];
    int tid = threadIdx.x;
    int warp = tid >> 5, lane = tid & 31;
    int row0 = blockIdx.x * 64;

    float acc[8][4];
#pragma unroll
    for (int r = 0; r < 8; r++)
#pragma unroll
        for (int c = 0; c < 4; c++) acc[r][c] = 0.f;

    for (int kt = 0; kt < 4; kt++) {
        // load W chunk: k rows [kt*32, kt*32+32), all 128 cols. 1024 float4.
        const float4* Wf4 = reinterpret_cast<const float4*>(W) + kt * 1024;
        for (int i = tid; i < 1024; i += 256)
            reinterpret_cast<float4*>(sW)[i] = __ldg(Wf4 + i);
        // load X tile: 64 rows x 32 k = 512 float4. sX layout [r][k].
        for (int i = tid; i < 512; i += 256) {
            int r = i >> 3, kk = i & 7;
            float4 v = make_float4(0.f, 0.f, 0.f, 0.f);
            if (row0 + r < nrows)
                v = __ldg(reinterpret_cast<const float4*>(X) + (size_t)(row0 + r) * 32 + kt * 8 + kk);
            reinterpret_cast<float4*>(sX)[i] = v;
        }
        __syncthreads();
#pragma unroll 8
        for (int k = 0; k < 32; k++) {
            float4 w = reinterpret_cast<const float4*>(sW + k * 128)[lane];
#pragma unroll
            for (int r = 0; r < 8; r++) {
                float xv = sX[(warp * 8 + r) * 32 + k];
                acc[r][0] += xv * w.x;
                acc[r][1] += xv * w.y;
                acc[r][2] += xv * w.z;
                acc[r][3] += xv * w.w;
            }
        }
        __syncthreads();
    }
#pragma unroll
    for (int r = 0; r < 8; r++) {
        int row = row0 + warp * 8 + r;
        if (row < nrows) {
            float4 v = make_float4(acc[r][0], acc[r][1], acc[r][2], acc[r][3]);
            *(reinterpret_cast<float4*>(H + (size_t)row * DD) + lane) = v;
        }
    }
}

// ---------------- scatter: one warp per edge, red.global.add.v4.f32 ----------------
__global__ __launch_bounds__(256) void k_scatter(const float* __restrict__ H,
                                                 const int* __restrict__ src,
                                                 const int* __restrict__ dst, int e) {
    int eidx = blockIdx.x * 8 + (threadIdx.x >> 5);
    if (eidx >= e) return;
    int lane = threadIdx.x & 31;
    int s = __ldg(src + eidx);
    int d = __ldg(dst + eidx);
    float norm = __ldg(g_dinv + s) * __ldg(g_dinv + d);
    float4 v = __ldg(reinterpret_cast<const float4*>(H + (size_t)s * DD) + lane);
    v.x *= norm; v.y *= norm; v.z *= norm; v.w *= norm;
    float* a = g_agg + (size_t)d * DD + lane * 4;
    asm volatile("red.global.add.v4.f32 [%0], {%1, %2, %3, %4};"
                 :: "l"(a), "f"(v.x), "f"(v.y), "f"(v.z), "f"(v.w)
                 : "memory");
}

// ---------------- combine: t = agg + h*dinv^2 + b ; accumulate col stats ----------------
// block: 128 threads (one per column), 64 rows per block.
__global__ __launch_bounds__(128) void k_combine(const float* __restrict__ bias, int n) {
    int col = threadIdx.x;
    int row0 = blockIdx.x * 64;
    int rend = min(row0 + 64, n);
    float b = __ldg(bias + col);
    float s = 0.f, ss = 0.f;
    for (int r = row0; r < rend; r++) {
        float di = __ldg(g_dinv + r);
        size_t idx = (size_t)r * DD + col;
        float t = g_agg[idx] + g_h[idx] * (di * di) + b;
        g_t[idx] = t;
        s += t;
        ss += t * t;
    }
    atomicAdd(&g_stats[col], s);
    atomicAdd(&g_stats[DD + col], ss);
}

// ---------------- finalize: scale/shift from stats, reset stats ----------------
__global__ void k_finalize(const float* __restrict__ gamma,
                           const float* __restrict__ beta, float inv_n) {
    int c = threadIdx.x;
    float s = g_stats[c], ss = g_stats[DD + c];
    float mu = s * inv_n;
    float var = ss * inv_n - mu * mu;
    float rstd = rsqrtf(var + 1e-5f);
    float sc = __ldg(gamma + c) * rstd;
    g_scale[c] = sc;
    g_shift[c] = __ldg(beta + c) - mu * sc;
    g_stats[c] = 0.f;
    g_stats[DD + c] = 0.f;
}

// ---------------- bn + (residual) + relu; optionally zero agg for next layer ----------------
__global__ __launch_bounds__(256) void k_bnrelu(float* __restrict__ out,
                                                const float* __restrict__ resid,
                                                int zero_agg, int n4) {
    int i = blockIdx.x * blockDim.x + threadIdx.x;
    if (i >= n4) return;
    int c4 = i & 31;
    float4 sc = reinterpret_cast<const float4*>(g_scale)[c4];
    float4 sh = reinterpret_cast<const float4*>(g_shift)[c4];
    float4 t = reinterpret_cast<const float4*>(g_t)[i];
    float4 r;
    r.x = t.x * sc.x + sh.x;
    r.y = t.y * sc.y + sh.y;
    r.z = t.z * sc.z + sh.z;
    r.w = t.w * sc.w + sh.w;
    if (resid) {
        float4 rv = __ldg(reinterpret_cast<const float4*>(resid) + i);
        r.x += rv.x; r.y += rv.y; r.z += rv.z; r.w += rv.w;
    }
    r.x = fmaxf(r.x, 0.f);
    r.y = fmaxf(r.y, 0.f);
    r.z = fmaxf(r.z, 0.f);
    r.w = fmaxf(r.w, 0.f);
    reinterpret_cast<float4*>(out)[i] = r;
    if (zero_agg) reinterpret_cast<float4*>(g_agg)[i] = make_float4(0.f, 0.f, 0.f, 0.f);
}

extern "C" void kernel_launch(void* const* d_in, const int* in_sizes, int n_in,
                              void* d_out, int out_size) {
    const float* x   = (const float*)d_in[0];
    const int*   ei  = (const int*)d_in[1];
    const float* W1  = (const float*)d_in[2];
    const float* b1  = (const float*)d_in[3];
    const float* ga1 = (const float*)d_in[4];
    const float* be1 = (const float*)d_in[5];
    const float* W2  = (const float*)d_in[6];
    const float* b2  = (const float*)d_in[7];
    const float* ga2 = (const float*)d_in[8];
    const float* be2 = (const float*)d_in[9];
    float* out = (float*)d_out;

    int n = in_sizes[0] / DD;
    int e = in_sizes[1] / 2;
    const int* src = ei;
    const int* dst = ei + e;

    int n4 = n * (DD / 4);
    float inv_n = 1.0f / (float)n;

    // device pointers to scratch (symbols referenced directly inside kernels)
    float *d_h, *d_y;
    cudaGetSymbolAddress((void**)&d_h, g_h);
    cudaGetSymbolAddress((void**)&d_y, g_y);

    dim3 b256(256), b128(128);
    int gInit = (n4 + 255) / 256;
    int gE    = (e + 255) / 256;
    int gN    = (n + 255) / 256;
    int gGemm = (n + 63) / 64;
    int gScat = (e + 7) / 8;
    int gComb = (n + 63) / 64;
    int gBn   = (n4 + 255) / 256;

    // ---- graph-structure prep ----
    k_init<<<gInit, b256>>>(n);
    k_degree<<<gE, b256>>>(dst, e);
    k_dinv<<<gN, b256>>>(n);

    // ---- layer 1 ----
    k_gemm<<<gGemm, b256>>>(x, W1, d_h, n);
    k_scatter<<<gScat, b256>>>(d_h, src, dst, e);
    k_combine<<<gComb, b128>>>(b1, n);
    k_finalize<<<1, b128>>>(ga1, be1, inv_n);
    k_bnrelu<<<gBn, b256>>>(d_y, nullptr, /*zero_agg=*/1, n4);

    // ---- layer 2 ----
    k_gemm<<<gGemm, b256>>>(d_y, W2, d_h, n);
    k_scatter<<<gScat, b256>>>(d_h, src, dst, e);
    k_combine<<<gComb, b128>>>(b2, n);
    k_finalize<<<1, b128>>>(ga2, be2, inv_n);
    k_bnrelu<<<gBn, b256>>>(out, /*resid=*/x, /*zero_agg=*/0, n4);
}